// round 1
// baseline (speedup 1.0000x reference)
#include <cuda_runtime.h>
#include <math.h>

// Problem dims
#define Lnum 6
#define Hn   12
#define Cn   768
#define Dn   64
#define Fn   3072
#define Vn   50257
#define Bn   8
#define Tn   1024

// ---------------- scratch (device globals; allocation-free) ----------------
__device__ float g_h0[Bn*Tn*Cn];
__device__ float g_h1[Bn*Tn*Cn];
__device__ float g_y [Bn*Tn*Cn];
__device__ float g_q [Bn*Tn*Cn];
__device__ float g_k [Bn*Tn*Cn];
__device__ float g_v [Bn*Tn*Cn];
__device__ float g_o [Bn*Tn*Cn];
__device__ float g_ff[Bn*Tn*Fn];
__device__ float g_hl[Bn*Cn];

// ---------------- embedding ----------------
__global__ void __launch_bounds__(256) embed_kernel(
    const int* __restrict__ x, const float* __restrict__ tok,
    const float* __restrict__ pos, float* __restrict__ h)
{
    int bt = blockIdx.x;              // 0 .. B*T-1
    int t  = bt & (Tn - 1);
    int tk = x[bt];
    const float* tp = tok + (size_t)tk * Cn;
    const float* pp = pos + (size_t)t  * Cn;
    float* hp = h + (size_t)bt * Cn;
    for (int c = threadIdx.x * 4; c < Cn; c += 256 * 4) {
        float4 a = *(const float4*)(tp + c);
        float4 b = *(const float4*)(pp + c);
        float4 r; r.x = a.x + b.x; r.y = a.y + b.y; r.z = a.z + b.z; r.w = a.w + b.w;
        *(float4*)(hp + c) = r;
    }
}

// ---------------- layernorm (row per block; mapped input row) ----------------
__global__ void __launch_bounds__(256) ln_kernel(
    const float* __restrict__ in, float* __restrict__ out,
    const float* __restrict__ w, const float* __restrict__ bi,
    int stride, int offset)
{
    int row = blockIdx.x;
    const float* xp = in + ((size_t)row * stride + offset) * Cn;
    int tid = threadIdx.x;
    float vals[3];
    float s = 0.f, s2 = 0.f;
    #pragma unroll
    for (int e = 0; e < 3; e++) {
        float v = xp[tid + e*256];
        vals[e] = v; s += v; s2 += v*v;
    }
    #pragma unroll
    for (int msk = 16; msk; msk >>= 1) {
        s  += __shfl_xor_sync(0xffffffffu, s,  msk);
        s2 += __shfl_xor_sync(0xffffffffu, s2, msk);
    }
    __shared__ float rs[8], rs2[8];
    int wid = tid >> 5, lane = tid & 31;
    if (lane == 0) { rs[wid] = s; rs2[wid] = s2; }
    __syncthreads();
    float S = 0.f, S2 = 0.f;
    #pragma unroll
    for (int i = 0; i < 8; i++) { S += rs[i]; S2 += rs2[i]; }
    float mean = S * (1.f/Cn);
    float var  = S2 * (1.f/Cn) - mean*mean;
    float inv  = rsqrtf(var + 1e-5f);
    float* op = out + (size_t)row * Cn;
    #pragma unroll
    for (int e = 0; e < 3; e++) {
        int c = tid + e*256;
        op[c] = (vals[e] - mean) * inv * w[c] + bi[c];
    }
}

// ---------------- generic SGEMM: Out[M,N] = A_mapped[M,K] @ W[K,N] (+bias)(+gelu)(+resid) ----
// A row r -> A + ((r/a_rpb)*a_bstr + a_off + r%a_rpb)*K
// headmode: W stored as [H][K][64]; block col-tile (BN=64) = exactly one head.
#define BM 128
#define BN 64
#define BK 16
__global__ void __launch_bounds__(256) sgemm_kernel(
    const float* __restrict__ A, int K, int a_rpb, int a_bstr, int a_off,
    const float* __restrict__ W, int N, int headmode,
    const float* __restrict__ bias,
    const float* __restrict__ Rsd, int r_rpb, int r_bstr, int r_off,
    float* __restrict__ Out, int do_gelu)
{
    __shared__ float As[BK][BM + 4];
    __shared__ float Bs[BK][BN];

    int m0 = blockIdx.x * BM;
    int n0 = blockIdx.y * BN;
    int tid = threadIdx.x;
    int tx = tid & 15, ty = tid >> 4;

    // A load mapping: 2 rows / thread, float4 along K
    int arow = tid >> 2;              // 0..63
    int kcol = (tid & 3) << 2;        // 0,4,8,12
    int r0 = m0 + arow, r1 = r0 + 64;
    const float* Ar0 = A + ((size_t)(r0 / a_rpb) * a_bstr + a_off + (r0 % a_rpb)) * K;
    const float* Ar1 = A + ((size_t)(r1 / a_rpb) * a_bstr + a_off + (r1 % a_rpb)) * K;

    // W load mapping
    int kb = tid >> 4;                // 0..15
    int nn = (tid & 15) << 2;         // 0..60
    const float* Wb; size_t ldw;
    if (headmode) { Wb = W + (size_t)(n0 >> 6) * K * 64 + nn; ldw = 64; }
    else          { Wb = W + n0 + nn;                          ldw = (size_t)N; }

    float acc[8][4];
    #pragma unroll
    for (int i = 0; i < 8; i++)
        #pragma unroll
        for (int j = 0; j < 4; j++) acc[i][j] = 0.f;

    for (int k0 = 0; k0 < K; k0 += BK) {
        float4 a0 = *(const float4*)(Ar0 + k0 + kcol);
        float4 a1 = *(const float4*)(Ar1 + k0 + kcol);
        As[kcol+0][arow] = a0.x; As[kcol+1][arow] = a0.y;
        As[kcol+2][arow] = a0.z; As[kcol+3][arow] = a0.w;
        As[kcol+0][arow+64] = a1.x; As[kcol+1][arow+64] = a1.y;
        As[kcol+2][arow+64] = a1.z; As[kcol+3][arow+64] = a1.w;
        float4 bv4 = *(const float4*)(Wb + (size_t)(k0 + kb) * ldw);
        *(float4*)&Bs[kb][nn] = bv4;
        __syncthreads();
        #pragma unroll
        for (int kk = 0; kk < BK; kk++) {
            float af[8], bf[4];
            #pragma unroll
            for (int i = 0; i < 8; i++) af[i] = As[kk][i*16 + ty];
            #pragma unroll
            for (int j = 0; j < 4; j++) bf[j] = Bs[kk][j*16 + tx];
            #pragma unroll
            for (int i = 0; i < 8; i++)
                #pragma unroll
                for (int j = 0; j < 4; j++) acc[i][j] += af[i] * bf[j];
        }
        __syncthreads();
    }

    #pragma unroll
    for (int j = 0; j < 4; j++) {
        int col = n0 + j*16 + tx;
        float bb = bias ? bias[col] : 0.f;
        #pragma unroll
        for (int i = 0; i < 8; i++) {
            int row = m0 + i*16 + ty;
            float vv = acc[i][j] + bb;
            if (do_gelu) vv = 0.5f * vv * (1.f + erff(vv * 0.70710678118654752f));
            if (Rsd) vv += Rsd[((size_t)(row / r_rpb) * r_bstr + r_off + (row % r_rpb)) * N + col];
            Out[(size_t)row * N + col] = vv;
        }
    }
}

// ---------------- fused attention (flash-style, 64x64 tiles, online softmax) -------------
#define ALD 68
#define ATTN_SMEM (3 * 64 * ALD * 4)
__global__ void __launch_bounds__(256) attn_kernel(
    const float* __restrict__ Qg, const float* __restrict__ Kg,
    const float* __restrict__ Vg, float* __restrict__ Og,
    int cut, int Ts, int off)
{
    extern __shared__ float sm[];
    float* Qs = sm;                 // [64][ALD]
    float* Ks = sm + 64*ALD;        // [64][ALD]  (K, then reused for V)
    float* Ps = sm + 2*64*ALD;      // [64][ALD]

    int b = blockIdx.z, h = blockIdx.y;
    int q0 = blockIdx.x * 64;
    int tid = threadIdx.x;
    int tx = tid & 15, ty = tid >> 4;

    {   // load Q tile
        int row = tid >> 2;
        int c0  = (tid & 3) << 4;
        const float* qp = Qg + (((size_t)(b*cut + q0 + row)) * Hn + h) * Dn + c0;
        float* dst = Qs + row*ALD + c0;
        #pragma unroll
        for (int e = 0; e < 4; e++)
            *(float4*)(dst + e*4) = *(const float4*)(qp + e*4);
    }

    float m[4], lsum[4], acc[4][4];
    #pragma unroll
    for (int i = 0; i < 4; i++) {
        m[i] = -1e30f; lsum[i] = 0.f;
        #pragma unroll
        for (int j = 0; j < 4; j++) acc[i][j] = 0.f;
    }

    const float scale = 0.03608439182435161f;   // 768^-0.5 (scale uses C, not D!)
    int nst = (off + q0) / 64 + 1;

    for (int st = 0; st < nst; st++) {
        int s0 = st * 64;
        __syncthreads();
        {   // load K tile
            int row = tid >> 2;
            int c0  = (tid & 3) << 4;
            const float* kp = Kg + (((size_t)(b*Ts + s0 + row)) * Hn + h) * Dn + c0;
            float* dst = Ks + row*ALD + c0;
            #pragma unroll
            for (int e = 0; e < 4; e++)
                *(float4*)(dst + e*4) = *(const float4*)(kp + e*4);
        }
        __syncthreads();

        // S = Q K^T  (4x4 per thread, K-dim = 64)
        float sacc[4][4];
        #pragma unroll
        for (int i = 0; i < 4; i++)
            #pragma unroll
            for (int j = 0; j < 4; j++) sacc[i][j] = 0.f;
        #pragma unroll
        for (int d4 = 0; d4 < 16; d4++) {
            float4 qv[4], kv[4];
            #pragma unroll
            for (int i = 0; i < 4; i++) qv[i] = *(const float4*)(Qs + (i*16+ty)*ALD + d4*4);
            #pragma unroll
            for (int j = 0; j < 4; j++) kv[j] = *(const float4*)(Ks + (j*16+tx)*ALD + d4*4);
            #pragma unroll
            for (int i = 0; i < 4; i++)
                #pragma unroll
                for (int j = 0; j < 4; j++)
                    sacc[i][j] += qv[i].x*kv[j].x + qv[i].y*kv[j].y
                                + qv[i].z*kv[j].z + qv[i].w*kv[j].w;
        }

        // online softmax per row
        #pragma unroll
        for (int i = 0; i < 4; i++) {
            int qi = i*16 + ty;
            int qabs = off + q0 + qi;
            float sv[4];
            float rmax = -1e30f;
            #pragma unroll
            for (int j = 0; j < 4; j++) {
                int sgl = s0 + j*16 + tx;
                sv[j] = (sgl <= qabs) ? sacc[i][j] * scale : -1e30f;
                rmax = fmaxf(rmax, sv[j]);
            }
            #pragma unroll
            for (int msk = 8; msk >= 1; msk >>= 1)
                rmax = fmaxf(rmax, __shfl_xor_sync(0xffffffffu, rmax, msk));
            float nm   = fmaxf(m[i], rmax);
            float corr = __expf(m[i] - nm);
            m[i] = nm;
            float rs = 0.f, p[4];
            #pragma unroll
            for (int j = 0; j < 4; j++) { p[j] = __expf(sv[j] - nm); rs += p[j]; }
            #pragma unroll
            for (int msk = 8; msk >= 1; msk >>= 1)
                rs += __shfl_xor_sync(0xffffffffu, rs, msk);
            lsum[i] = lsum[i] * corr + rs;
            #pragma unroll
            for (int j = 0; j < 4; j++) {
                acc[i][j] *= corr;
                Ps[qi*ALD + j*16 + tx] = p[j];
            }
        }
        __syncthreads();          // Ks reads (S) done; Ps visible

        {   // load V tile into Ks
            int row = tid >> 2;
            int c0  = (tid & 3) << 4;
            const float* vp = Vg + (((size_t)(b*Ts + s0 + row)) * Hn + h) * Dn + c0;
            float* dst = Ks + row*ALD + c0;
            #pragma unroll
            for (int e = 0; e < 4; e++)
                *(float4*)(dst + e*4) = *(const float4*)(vp + e*4);
        }
        __syncthreads();

        // O += P V
        #pragma unroll 4
        for (int ss = 0; ss < 64; ss++) {
            float pb[4], vb[4];
            #pragma unroll
            for (int i = 0; i < 4; i++) pb[i] = Ps[(i*16+ty)*ALD + ss];
            #pragma unroll
            for (int j = 0; j < 4; j++) vb[j] = Ks[ss*ALD + j*16 + tx];
            #pragma unroll
            for (int i = 0; i < 4; i++)
                #pragma unroll
                for (int j = 0; j < 4; j++) acc[i][j] += pb[i] * vb[j];
        }
    }

    #pragma unroll
    for (int i = 0; i < 4; i++) {
        float inv = 1.f / lsum[i];
        int qi = i*16 + ty;
        #pragma unroll
        for (int j = 0; j < 4; j++)
            Og[(((size_t)(b*cut + q0 + qi)) * Hn + h) * Dn + j*16 + tx] = acc[i][j] * inv;
    }
}

// ---------------- final logits: out[b,v] = hl[b,:] . Wout[:,v] + bout[v] --------------
__global__ void __launch_bounds__(256) logits_kernel(
    const float* __restrict__ hl, const float* __restrict__ Wout,
    const float* __restrict__ bout, float* __restrict__ out)
{
    __shared__ float sh[Bn * Cn];
    int tid = threadIdx.x;
    for (int i = tid; i < Bn*Cn; i += 256) sh[i] = hl[i];
    __syncthreads();
    int v = blockIdx.x * 256 + tid;
    if (v >= Vn) return;
    float bb = bout[v];
    float acc[Bn];
    #pragma unroll
    for (int b2 = 0; b2 < Bn; b2++) acc[b2] = bb;
    const float* wp = Wout + v;
    #pragma unroll 4
    for (int c = 0; c < Cn; c++) {
        float wv = wp[(size_t)c * Vn];
        #pragma unroll
        for (int b2 = 0; b2 < Bn; b2++) acc[b2] += sh[b2*Cn + c] * wv;
    }
    #pragma unroll
    for (int b2 = 0; b2 < Bn; b2++) out[(size_t)b2 * Vn + v] = acc[b2];
}

// ---------------- launch ----------------
extern "C" void kernel_launch(void* const* d_in, const int* in_sizes, int n_in,
                              void* d_out, int out_size)
{
    const int*   x     = (const int*)  d_in[0];
    const float* tok   = (const float*)d_in[1];
    const float* pos   = (const float*)d_in[2];
    const float* Wq    = (const float*)d_in[3];
    const float* bq    = (const float*)d_in[4];
    const float* Wk    = (const float*)d_in[5];
    const float* bk    = (const float*)d_in[6];
    const float* Wv    = (const float*)d_in[7];
    const float* bv    = (const float*)d_in[8];
    const float* Wproj = (const float*)d_in[9];
    const float* bproj = (const float*)d_in[10];
    const float* ln1w  = (const float*)d_in[11];
    const float* ln1b  = (const float*)d_in[12];
    const float* ln2w  = (const float*)d_in[13];
    const float* ln2b  = (const float*)d_in[14];
    const float* Wff1  = (const float*)d_in[15];
    const float* bff1  = (const float*)d_in[16];
    const float* Wff2  = (const float*)d_in[17];
    const float* bff2  = (const float*)d_in[18];
    const float* lnfw  = (const float*)d_in[19];
    const float* lnfb  = (const float*)d_in[20];
    const float* Wout  = (const float*)d_in[21];
    const float* bout  = (const float*)d_in[22];
    float* out = (float*)d_out;
    (void)in_sizes; (void)n_in; (void)out_size;

    float *h0,*h1,*y,*q,*k,*v,*o,*ff,*hl;
    cudaGetSymbolAddress((void**)&h0, g_h0);
    cudaGetSymbolAddress((void**)&h1, g_h1);
    cudaGetSymbolAddress((void**)&y,  g_y);
    cudaGetSymbolAddress((void**)&q,  g_q);
    cudaGetSymbolAddress((void**)&k,  g_k);
    cudaGetSymbolAddress((void**)&v,  g_v);
    cudaGetSymbolAddress((void**)&o,  g_o);
    cudaGetSymbolAddress((void**)&ff, g_ff);
    cudaGetSymbolAddress((void**)&hl, g_hl);

    cudaFuncSetAttribute(attn_kernel, cudaFuncAttributeMaxDynamicSharedMemorySize, ATTN_SMEM);

    embed_kernel<<<Bn*Tn, 256>>>(x, tok, pos, h0);

    int Tc = Tn;
    for (int l = 0; l < Lnum; l++) {
        int fade = (l != 0 && l != Lnum-1);
        int half = Tn >> l;
        int cut  = fade ? (Tc < half ? Tc : half) : Tc;
        int off  = Tc - cut;

        ln_kernel<<<Bn*Tc, 256>>>(h0, y, ln1w + l*Cn, ln1b + l*Cn, 1, 0);

        dim3 gq(Bn*cut/BM, Cn/BN);
        sgemm_kernel<<<gq, 256>>>(y, Cn, cut, Tc, off,
                                  Wq + (size_t)l*Hn*Cn*Dn, Cn, 1, bq + l*Hn*Dn,
                                  nullptr, 1, 1, 0, q, 0);
        dim3 gkv(Bn*Tc/BM, Cn/BN);
        sgemm_kernel<<<gkv, 256>>>(y, Cn, Tc, Tc, 0,
                                   Wk + (size_t)l*Hn*Cn*Dn, Cn, 1, bk + l*Hn*Dn,
                                   nullptr, 1, 1, 0, k, 0);
        sgemm_kernel<<<gkv, 256>>>(y, Cn, Tc, Tc, 0,
                                   Wv + (size_t)l*Hn*Cn*Dn, Cn, 1, bv + l*Hn*Dn,
                                   nullptr, 1, 1, 0, v, 0);

        dim3 ga(cut/64, Hn, Bn);
        attn_kernel<<<ga, 256, ATTN_SMEM>>>(q, k, v, o, cut, Tc, off);

        dim3 gp(Bn*cut/BM, Cn/BN);
        sgemm_kernel<<<gp, 256>>>(o, Cn, cut, cut, 0,
                                  Wproj + (size_t)l*Cn*Cn, Cn, 0, bproj + l*Cn,
                                  h0, cut, Tc, off, h1, 0);

        ln_kernel<<<Bn*cut, 256>>>(h1, y, ln2w + l*Cn, ln2b + l*Cn, 1, 0);

        dim3 g1(Bn*cut/BM, Fn/BN);
        sgemm_kernel<<<g1, 256>>>(y, Cn, cut, cut, 0,
                                  Wff1 + (size_t)l*Cn*Fn, Fn, 0, bff1 + l*Fn,
                                  nullptr, 1, 1, 0, ff, 1);
        dim3 g2(Bn*cut/BM, Cn/BN);
        sgemm_kernel<<<g2, 256>>>(ff, Fn, cut, cut, 0,
                                  Wff2 + (size_t)l*Fn*Cn, Cn, 0, bff2 + l*Cn,
                                  h1, cut, cut, 0, h0, 0);
        Tc = cut;
    }

    // final LN on last token only, then logits
    ln_kernel<<<Bn, 256>>>(h0, hl, lnfw, lnfb, Tc, Tc - 1);
    logits_kernel<<<(Vn + 255)/256, 256>>>(hl, Wout, bout, out);
}